// round 11
// baseline (speedup 1.0000x reference)
#include <cuda_runtime.h>
#include <math.h>
#include <cstdint>

#define NN 100000     // nodes
#define NE 800000     // edges
#define FD 128        // feature dim (in = hidden = 128)
#define NG 128        // graphs
#define NC 10         // classes
#define BN_EPS 1e-5f

// ---------------- device scratch (no allocation allowed) ----------------
__device__ float g_bufA[(size_t)NN * FD];   // aggregation accumulator / GEMM input
__device__ float g_bufB[(size_t)NN * FD];   // MLP hidden
__device__ float g_bufC[(size_t)NN * FD];   // MLP out (pre-BN)
__device__ float g_bufD[(size_t)NN * FD];   // post BN+ReLU (gather source, conv2)
__device__ float g_sum[FD];
__device__ float g_sumsq[FD];
__device__ float g_scale[FD];
__device__ float g_shift[FD];
__device__ float g_pooled[NG * FD];
__device__ float g_counts[NG];
// CSR build scratch
__device__ int g_deg[NN];
__device__ int g_startO[NN + 1];
__device__ int g_cursor[NN];
__device__ int g_srcs[NE];

// ================= CSR build (per launch; reused by both convs) =================
__global__ void zero_deg_k() {
    int i = blockIdx.x * blockDim.x + threadIdx.x;
    if (i < NN) g_deg[i] = 0;
}

__global__ void hist_k(const int* __restrict__ ei) {
    int e = blockIdx.x * blockDim.x + threadIdx.x;
    if (e >= NE) return;
    int d = ei[NE + e];
    if ((unsigned)d < NN) atomicAdd(&g_deg[d], 1);
}

// single-block exclusive scan over 100K degrees (1024 threads, ~98 elems each)
__global__ void scan_k() {
    const int T = 1024;
    int t = threadIdx.x;
    const int chunk = (NN + T - 1) / T;
    int c0 = t * chunk;
    int c1 = min(c0 + chunk, NN);
    int local = 0;
    for (int i = c0; i < c1; i++) local += g_deg[i];

    int lane = t & 31, w = t >> 5;
    int v = local;
    #pragma unroll
    for (int o = 1; o < 32; o <<= 1) {
        int n = __shfl_up_sync(~0u, v, o);
        if (lane >= o) v += n;
    }
    __shared__ int wsum[32];
    if (lane == 31) wsum[w] = v;
    __syncthreads();
    if (w == 0) {
        int s = wsum[lane];
        #pragma unroll
        for (int o = 1; o < 32; o <<= 1) {
            int n = __shfl_up_sync(~0u, s, o);
            if (lane >= o) s += n;
        }
        wsum[lane] = s;
    }
    __syncthreads();
    int excl = v - local + (w > 0 ? wsum[w - 1] : 0);
    int run = excl;
    for (int i = c0; i < c1; i++) {
        int d = g_deg[i];
        g_startO[i] = run;
        g_cursor[i] = run;
        run += d;
    }
    if (t == T - 1) g_startO[NN] = run;
}

__global__ void fill_k(const int* __restrict__ ei) {
    int e = blockIdx.x * blockDim.x + threadIdx.x;
    if (e >= NE) return;
    int s = ei[e];
    int d = ei[NE + e];
    if ((unsigned)s >= NN || (unsigned)d >= NN) return;
    int pos = atomicAdd(&g_cursor[d], 1);
    g_srcs[pos] = s;
}

// ---------------- CSR gather aggregation: out[n] = base[n] + sum_{s in N(n)} feat[s] ----
// one warp per node; lane holds one float4 (512B row per warp, coalesced)
__global__ void gather_k(const float4* __restrict__ feat, const float4* __restrict__ base,
                         float4* __restrict__ out) {
    int warp = (blockIdx.x * blockDim.x + threadIdx.x) >> 5;
    if (warp >= NN) return;
    int lane = threadIdx.x & 31;
    float4 acc = base[(size_t)warp * 32 + lane];
    int j0 = g_startO[warp], j1 = g_startO[warp + 1];
    int j = j0;
    for (; j + 1 < j1; j += 2) {   // unroll-2: MLP=2
        int s0 = g_srcs[j], s1 = g_srcs[j + 1];
        float4 v0 = feat[(size_t)s0 * 32 + lane];
        float4 v1 = feat[(size_t)s1 * 32 + lane];
        acc.x += v0.x + v1.x; acc.y += v0.y + v1.y;
        acc.z += v0.z + v1.z; acc.w += v0.w + v1.w;
    }
    if (j < j1) {
        int s0 = g_srcs[j];
        float4 v0 = feat[(size_t)s0 * 32 + lane];
        acc.x += v0.x; acc.y += v0.y; acc.z += v0.z; acc.w += v0.w;
    }
    out[(size_t)warp * 32 + lane] = acc;
}

// ================= tf32 mma.sync GEMM (arch-agnostic PTX, works on compute_103) ========
#define SM_STRIDE 136
#define SM_TILE (128 * SM_STRIDE)            // floats per tile
#define GEMM_SMEM ((2 * SM_TILE + FD) * 4)   // A + W + bias

__device__ __forceinline__ uint32_t f2tf32(float f) {
    uint32_t u;
    asm("cvt.rna.tf32.f32 %0, %1;" : "=r"(u) : "f"(f));
    return u;
}

#define MMA_TF32(Cf, Af, Bf)                                                   \
    asm volatile("mma.sync.aligned.m16n8k8.row.col.f32.tf32.tf32.f32 "         \
                 "{%0,%1,%2,%3}, {%4,%5,%6,%7}, {%8,%9}, {%0,%1,%2,%3};"       \
                 : "+f"((Cf)[0]), "+f"((Cf)[1]), "+f"((Cf)[2]), "+f"((Cf)[3])  \
                 : "r"((Af)[0]), "r"((Af)[1]), "r"((Af)[2]), "r"((Af)[3]),     \
                   "r"((Bf)[0]), "r"((Bf)[1]))

__global__ void __launch_bounds__(256, 1)
gemm_tc_k(const float* __restrict__ A, const float* __restrict__ W,
          const float* __restrict__ bias, float* __restrict__ C, int relu) {
    extern __shared__ float sh[];
    float* As = sh;                  // [128][136] tf32 bit patterns
    float* Ws = sh + SM_TILE;        // [128][136]
    float* bs = sh + 2 * SM_TILE;    // [128]

    int tid = threadIdx.x;
    int wid = tid >> 5;
    int lid = tid & 31;
    int row0 = blockIdx.x * 128;

    if (tid < FD) bs[tid] = bias[tid];

    const float4* A4 = (const float4*)A;
    const float4* W4 = (const float4*)W;
    #pragma unroll
    for (int it = 0; it < 16; it++) {
        int r = it * 8 + wid;
        int gr = row0 + r;
        float4 v = (gr < NN) ? A4[(size_t)gr * 32 + lid] : make_float4(0.f, 0.f, 0.f, 0.f);
        uint4 t;
        t.x = f2tf32(v.x); t.y = f2tf32(v.y); t.z = f2tf32(v.z); t.w = f2tf32(v.w);
        *(uint4*)&As[r * SM_STRIDE + lid * 4] = t;

        float4 w = W4[(size_t)r * 32 + lid];
        uint4 tw;
        tw.x = f2tf32(w.x); tw.y = f2tf32(w.y); tw.z = f2tf32(w.z); tw.w = f2tf32(w.w);
        *(uint4*)&Ws[r * SM_STRIDE + lid * 4] = tw;
    }
    __syncthreads();

    int warp_m = wid & 3;
    int warp_n = wid >> 2;
    int tig = lid & 3;
    int gid = lid >> 2;

    float c[2][8][4];
    #pragma unroll
    for (int mt = 0; mt < 2; mt++)
        #pragma unroll
        for (int nt = 0; nt < 8; nt++)
            #pragma unroll
            for (int j = 0; j < 4; j++) c[mt][nt][j] = 0.f;

    #pragma unroll 4
    for (int k0 = 0; k0 < 16; k0++) {
        int kc = k0 * 8 + tig;
        uint32_t a[2][4];
        #pragma unroll
        for (int mt = 0; mt < 2; mt++) {
            int rb = warp_m * 32 + mt * 16 + gid;
            a[mt][0] = __float_as_uint(As[rb * SM_STRIDE + kc]);
            a[mt][1] = __float_as_uint(As[(rb + 8) * SM_STRIDE + kc]);
            a[mt][2] = __float_as_uint(As[rb * SM_STRIDE + kc + 4]);
            a[mt][3] = __float_as_uint(As[(rb + 8) * SM_STRIDE + kc + 4]);
        }
        uint32_t b[8][2];
        #pragma unroll
        for (int nt = 0; nt < 8; nt++) {
            int n = warp_n * 64 + nt * 8 + gid;
            b[nt][0] = __float_as_uint(Ws[kc * SM_STRIDE + n]);
            b[nt][1] = __float_as_uint(Ws[(kc + 4) * SM_STRIDE + n]);
        }
        #pragma unroll
        for (int mt = 0; mt < 2; mt++)
            #pragma unroll
            for (int nt = 0; nt < 8; nt++)
                MMA_TF32(c[mt][nt], a[mt], b[nt]);
    }

    #pragma unroll
    for (int mt = 0; mt < 2; mt++) {
        int rg = row0 + warp_m * 32 + mt * 16 + gid;
        #pragma unroll
        for (int nt = 0; nt < 8; nt++) {
            int col = warp_n * 64 + nt * 8 + tig * 2;
            float2 o0, o1;
            o0.x = c[mt][nt][0] + bs[col];
            o0.y = c[mt][nt][1] + bs[col + 1];
            o1.x = c[mt][nt][2] + bs[col];
            o1.y = c[mt][nt][3] + bs[col + 1];
            if (relu) {
                o0.x = fmaxf(o0.x, 0.f); o0.y = fmaxf(o0.y, 0.f);
                o1.x = fmaxf(o1.x, 0.f); o1.y = fmaxf(o1.y, 0.f);
            }
            if (rg < NN)     *(float2*)&C[(size_t)rg * FD + col] = o0;
            if (rg + 8 < NN) *(float2*)&C[(size_t)(rg + 8) * FD + col] = o1;
        }
    }
}

// ---------------- small zero kernels ----------------
__global__ void zero_all_k() {
    int i = blockIdx.x * blockDim.x + threadIdx.x;
    if (i < FD) { g_sum[i] = 0.f; g_sumsq[i] = 0.f; }
    if (i < NG) g_counts[i] = 0.f;
    if (i < NG * FD) g_pooled[i] = 0.f;
}

__global__ void zero_sums_k() {
    int i = threadIdx.x;
    if (i < FD) { g_sum[i] = 0.f; g_sumsq[i] = 0.f; }
}

// ---------------- BN statistics ----------------
__global__ void bnstats_k(const float* __restrict__ X) {
    int f = threadIdx.x;
    int chunk = (NN + gridDim.x - 1) / gridDim.x;
    int r0 = blockIdx.x * chunk;
    int r1 = min(r0 + chunk, NN);
    float a = 0.f, b = 0.f;
    for (int r = r0; r < r1; r++) {
        float v = X[(size_t)r * FD + f];
        a += v;
        b = fmaf(v, v, b);
    }
    atomicAdd(&g_sum[f], a);
    atomicAdd(&g_sumsq[f], b);
}

// ---------------- BN finalize ----------------
__global__ void bnfin_k(const float* __restrict__ gamma, const float* __restrict__ beta) {
    int f = threadIdx.x;
    float mean = g_sum[f] * (1.f / NN);
    float var = g_sumsq[f] * (1.f / NN) - mean * mean;
    float sc = gamma[f] * rsqrtf(var + BN_EPS);
    g_scale[f] = sc;
    g_shift[f] = beta[f] - mean * sc;
}

// ---------------- BN+ReLU (single output; gather reads it for self+neighbors) ----------
__global__ void bnrelu_k(const float4* __restrict__ X, float4* __restrict__ o1) {
    int i = blockIdx.x * blockDim.x + threadIdx.x;
    if (i >= NN * 32) return;
    int f = i & 31;
    float4 sc = ((const float4*)g_scale)[f];
    float4 sf = ((const float4*)g_shift)[f];
    float4 x = X[i];
    float4 v;
    v.x = fmaxf(fmaf(x.x, sc.x, sf.x), 0.f);
    v.y = fmaxf(fmaf(x.y, sc.y, sf.y), 0.f);
    v.z = fmaxf(fmaf(x.z, sc.z, sf.z), 0.f);
    v.w = fmaxf(fmaf(x.w, sc.w, sf.w), 0.f);
    o1[i] = v;
}

// ---------------- BN+ReLU fused with graph pooling ----------------
__global__ void bnpool_k(const float4* __restrict__ X, const int* __restrict__ batch) {
    int i = blockIdx.x * blockDim.x + threadIdx.x;
    if (i >= NN * 32) return;
    int f = i & 31;
    int node = i >> 5;
    float4 sc = ((const float4*)g_scale)[f];
    float4 sf = ((const float4*)g_shift)[f];
    float4 x = X[i];
    float4 v;
    v.x = fmaxf(fmaf(x.x, sc.x, sf.x), 0.f);
    v.y = fmaxf(fmaf(x.y, sc.y, sf.y), 0.f);
    v.z = fmaxf(fmaf(x.z, sc.z, sf.z), 0.f);
    v.w = fmaxf(fmaf(x.w, sc.w, sf.w), 0.f);
    int g = batch[node];
    if ((unsigned)g >= NG) return;
    float* p = g_pooled + (size_t)g * FD + f * 4;
    asm volatile("red.global.add.v4.f32 [%0], {%1, %2, %3, %4};"
                 :: "l"(p), "f"(v.x), "f"(v.y), "f"(v.z), "f"(v.w) : "memory");
}

// ---------------- per-graph node counts ----------------
__global__ void count_k(const int* __restrict__ batch) {
    int i = blockIdx.x * blockDim.x + threadIdx.x;
    if (i < NN) {
        int g = batch[i];
        if ((unsigned)g < NG) atomicAdd(&g_counts[g], 1.f);
    }
}

// ---------------- classifier + log_softmax ----------------
__global__ void final_k(const float* __restrict__ Wlin, const float* __restrict__ blin,
                        float* __restrict__ out) {
    __shared__ float Ws[FD * NC];
    __shared__ float bs[NC];
    int t = threadIdx.x;
    for (int i = t; i < FD * NC; i += 128) Ws[i] = Wlin[i];
    if (t < NC) bs[t] = blin[t];
    __syncthreads();

    int g = t;
    float inv = 1.f / fmaxf(g_counts[g], 1.f);
    float logits[NC];
    #pragma unroll
    for (int c = 0; c < NC; c++) logits[c] = bs[c];
    for (int k = 0; k < FD; k++) {
        float p = g_pooled[(size_t)g * FD + k] * inv;
        #pragma unroll
        for (int c = 0; c < NC; c++) logits[c] = fmaf(p, Ws[k * NC + c], logits[c]);
    }
    float m = logits[0];
    #pragma unroll
    for (int c = 1; c < NC; c++) m = fmaxf(m, logits[c]);
    float s = 0.f;
    #pragma unroll
    for (int c = 0; c < NC; c++) s += expf(logits[c] - m);
    float lse = m + logf(s);
    #pragma unroll
    for (int c = 0; c < NC; c++) out[(size_t)g * NC + c] = logits[c] - lse;
}

// ---------------- host launcher ----------------
extern "C" void kernel_launch(void* const* d_in, const int* in_sizes, int n_in,
                              void* d_out, int out_size) {
    const float* x = (const float*)d_in[0];
    const int* ei = (const int*)d_in[1];
    const int* batch = (const int*)d_in[2];
    const float* W1a = (const float*)d_in[3];
    const float* b1a = (const float*)d_in[4];
    const float* W1b = (const float*)d_in[5];
    const float* b1b = (const float*)d_in[6];
    const float* gamma1 = (const float*)d_in[7];
    const float* beta1 = (const float*)d_in[8];
    const float* W2a = (const float*)d_in[9];
    const float* b2a = (const float*)d_in[10];
    const float* W2b = (const float*)d_in[11];
    const float* b2b = (const float*)d_in[12];
    const float* gamma2 = (const float*)d_in[13];
    const float* beta2 = (const float*)d_in[14];
    const float* Wlin = (const float*)d_in[15];
    const float* blin = (const float*)d_in[16];
    float* out = (float*)d_out;

    float *bufA, *bufB, *bufC, *bufD;
    cudaGetSymbolAddress((void**)&bufA, g_bufA);
    cudaGetSymbolAddress((void**)&bufB, g_bufB);
    cudaGetSymbolAddress((void**)&bufC, g_bufC);
    cudaGetSymbolAddress((void**)&bufD, g_bufD);

    cudaFuncSetAttribute(gemm_tc_k, cudaFuncAttributeMaxDynamicSharedMemorySize, GEMM_SMEM);

    const int n4 = NN * 32;
    const int EW_BLOCKS = (n4 + 255) / 256;
    const int E_BLOCKS = (NE + 255) / 256;
    const int TC_BLOCKS = (NN + 127) / 128;
    const int GA_BLOCKS = (NN * 32 + 255) / 256;   // one warp per node

    zero_all_k<<<(NG * FD + 255) / 256, 256>>>();

    // ---- build dst-sorted CSR once; reused by both convs ----
    zero_deg_k<<<(NN + 255) / 256, 256>>>();
    hist_k<<<E_BLOCKS, 256>>>(ei);
    scan_k<<<1, 1024>>>();
    fill_k<<<E_BLOCKS, 256>>>(ei);

    // ---- conv1 ----
    gather_k<<<GA_BLOCKS, 256>>>((const float4*)x, (const float4*)x, (float4*)bufA);
    gemm_tc_k<<<TC_BLOCKS, 256, GEMM_SMEM>>>(bufA, W1a, b1a, bufB, 1);
    gemm_tc_k<<<TC_BLOCKS, 256, GEMM_SMEM>>>(bufB, W1b, b1b, bufC, 0);
    bnstats_k<<<800, 128>>>(bufC);
    bnfin_k<<<1, 128>>>(gamma1, beta1);
    zero_sums_k<<<1, 128>>>();
    bnrelu_k<<<EW_BLOCKS, 256>>>((const float4*)bufC, (float4*)bufD);

    // ---- conv2 ----
    gather_k<<<GA_BLOCKS, 256>>>((const float4*)bufD, (const float4*)bufD, (float4*)bufA);
    gemm_tc_k<<<TC_BLOCKS, 256, GEMM_SMEM>>>(bufA, W2a, b2a, bufB, 1);
    gemm_tc_k<<<TC_BLOCKS, 256, GEMM_SMEM>>>(bufB, W2b, b2b, bufC, 0);
    bnstats_k<<<800, 128>>>(bufC);
    bnfin_k<<<1, 128>>>(gamma2, beta2);

    // ---- BN+ReLU fused with pooling, then classifier ----
    bnpool_k<<<EW_BLOCKS, 256>>>((const float4*)bufC, batch);
    count_k<<<(NN + 255) / 256, 256>>>(batch);
    final_k<<<1, 128>>>(Wlin, blin, out);
}

// round 12
// speedup vs baseline: 1.3712x; 1.3712x over previous
#include <cuda_runtime.h>
#include <math.h>
#include <cstdint>

#define NN 100000     // nodes
#define NE 800000     // edges
#define FD 128        // feature dim (in = hidden = 128)
#define NG 128        // graphs
#define NC 10         // classes
#define BN_EPS 1e-5f

// ---------------- device scratch (no allocation allowed) ----------------
__device__ float g_bufA[(size_t)NN * FD];   // aggregation accumulator / GEMM input
__device__ float g_bufB[(size_t)NN * FD];   // MLP hidden
__device__ float g_bufC[(size_t)NN * FD];   // MLP out (pre-BN)
__device__ float g_bufD[(size_t)NN * FD];   // post BN+ReLU (gather source, conv2)
__device__ float g_sum[FD];
__device__ float g_sumsq[FD];
__device__ float g_scale[FD];
__device__ float g_shift[FD];
__device__ float g_pooled[NG * FD];
__device__ float g_counts[NG];
// CSR build scratch
#define SCAN_BLK 512
#define SCAN_NB ((NN + SCAN_BLK - 1) / SCAN_BLK)   // 196
__device__ int g_deg[NN];
__device__ int g_startO[NN + 1];
__device__ int g_cursor[NN];
__device__ int g_srcs[NE];
__device__ int g_partial[SCAN_NB];

// ================= CSR build (per launch; reused by both convs) =================
__global__ void zero_deg_k() {
    int i = blockIdx.x * blockDim.x + threadIdx.x;
    if (i < NN) g_deg[i] = 0;
}

__global__ void hist_k(const int* __restrict__ ei) {
    int e = blockIdx.x * blockDim.x + threadIdx.x;
    if (e >= NE) return;
    int d = ei[NE + e];
    if ((unsigned)d < NN) atomicAdd(&g_deg[d], 1);
}

// ---- 3-phase parallel exclusive scan over g_deg ----
// phase 1: per-block partial sums (196 blocks x 512 threads)
__global__ void scanp1_k() {
    int t = threadIdx.x;
    int i = blockIdx.x * SCAN_BLK + t;
    int v = (i < NN) ? g_deg[i] : 0;
    #pragma unroll
    for (int o = 16; o; o >>= 1) v += __shfl_down_sync(~0u, v, o);
    __shared__ int ws[16];
    if ((t & 31) == 0) ws[t >> 5] = v;
    __syncthreads();
    if (t < 16) {
        int s = ws[t];
        #pragma unroll
        for (int o = 8; o; o >>= 1) s += __shfl_down_sync(0xffffu, s, o);
        if (t == 0) g_partial[blockIdx.x] = s;
    }
}

// phase 2: exclusive scan of the 196 partials (1 block, 256 threads)
__global__ void scanp2_k() {
    int t = threadIdx.x;
    int lane = t & 31, w = t >> 5;
    int v = (t < SCAN_NB) ? g_partial[t] : 0;
    int x = v;
    #pragma unroll
    for (int o = 1; o < 32; o <<= 1) {
        int n = __shfl_up_sync(~0u, x, o);
        if (lane >= o) x += n;
    }
    __shared__ int ws[8];
    if (lane == 31) ws[w] = x;
    __syncthreads();
    if (w == 0) {
        int s = (lane < 8) ? ws[lane] : 0;
        #pragma unroll
        for (int o = 1; o < 8; o <<= 1) {
            int n = __shfl_up_sync(~0u, s, o);
            if (lane >= o) s += n;
        }
        if (lane < 8) ws[lane] = s;
    }
    __syncthreads();
    int incl = x + (w > 0 ? ws[w - 1] : 0);
    if (t < SCAN_NB) g_partial[t] = incl - v;     // exclusive block offset
    if (t == SCAN_NB - 1) g_startO[NN] = incl;    // total valid edges
}

// phase 3: intra-block exclusive scan + block offset -> startO / cursor
__global__ void scanp3_k() {
    int t = threadIdx.x;
    int i = blockIdx.x * SCAN_BLK + t;
    int lane = t & 31, w = t >> 5;
    int v = (i < NN) ? g_deg[i] : 0;
    int x = v;
    #pragma unroll
    for (int o = 1; o < 32; o <<= 1) {
        int n = __shfl_up_sync(~0u, x, o);
        if (lane >= o) x += n;
    }
    __shared__ int ws[16];
    if (lane == 31) ws[w] = x;
    __syncthreads();
    if (w == 0) {
        int s = (lane < 16) ? ws[lane] : 0;
        #pragma unroll
        for (int o = 1; o < 16; o <<= 1) {
            int n = __shfl_up_sync(~0u, s, o);
            if (lane >= o) s += n;
        }
        if (lane < 16) ws[lane] = s;
    }
    __syncthreads();
    int excl = x - v + (w > 0 ? ws[w - 1] : 0) + g_partial[blockIdx.x];
    if (i < NN) { g_startO[i] = excl; g_cursor[i] = excl; }
}

__global__ void fill_k(const int* __restrict__ ei) {
    int e = blockIdx.x * blockDim.x + threadIdx.x;
    if (e >= NE) return;
    int s = ei[e];
    int d = ei[NE + e];
    if ((unsigned)s >= NN || (unsigned)d >= NN) return;
    int pos = atomicAdd(&g_cursor[d], 1);
    g_srcs[pos] = s;
}

// ---------------- CSR gather aggregation: out[n] = base[n] + sum_{s in N(n)} feat[s] ----
// one warp per node; lane holds one float4 (512B row per warp, coalesced)
__global__ void gather_k(const float4* __restrict__ feat, const float4* __restrict__ base,
                         float4* __restrict__ out) {
    int warp = (blockIdx.x * blockDim.x + threadIdx.x) >> 5;
    if (warp >= NN) return;
    int lane = threadIdx.x & 31;
    float4 acc = base[(size_t)warp * 32 + lane];
    int j0 = g_startO[warp], j1 = g_startO[warp + 1];
    int j = j0;
    for (; j + 1 < j1; j += 2) {   // unroll-2: MLP=2
        int s0 = g_srcs[j], s1 = g_srcs[j + 1];
        float4 v0 = feat[(size_t)s0 * 32 + lane];
        float4 v1 = feat[(size_t)s1 * 32 + lane];
        acc.x += v0.x + v1.x; acc.y += v0.y + v1.y;
        acc.z += v0.z + v1.z; acc.w += v0.w + v1.w;
    }
    if (j < j1) {
        int s0 = g_srcs[j];
        float4 v0 = feat[(size_t)s0 * 32 + lane];
        acc.x += v0.x; acc.y += v0.y; acc.z += v0.z; acc.w += v0.w;
    }
    out[(size_t)warp * 32 + lane] = acc;
}

// ================= tf32 mma.sync GEMM (arch-agnostic PTX, works on compute_103) ========
#define SM_STRIDE 136
#define SM_TILE (128 * SM_STRIDE)            // floats per tile
#define GEMM_SMEM ((2 * SM_TILE + FD) * 4)   // A + W + bias

__device__ __forceinline__ uint32_t f2tf32(float f) {
    uint32_t u;
    asm("cvt.rna.tf32.f32 %0, %1;" : "=r"(u) : "f"(f));
    return u;
}

#define MMA_TF32(Cf, Af, Bf)                                                   \
    asm volatile("mma.sync.aligned.m16n8k8.row.col.f32.tf32.tf32.f32 "         \
                 "{%0,%1,%2,%3}, {%4,%5,%6,%7}, {%8,%9}, {%0,%1,%2,%3};"       \
                 : "+f"((Cf)[0]), "+f"((Cf)[1]), "+f"((Cf)[2]), "+f"((Cf)[3])  \
                 : "r"((Af)[0]), "r"((Af)[1]), "r"((Af)[2]), "r"((Af)[3]),     \
                   "r"((Bf)[0]), "r"((Bf)[1]))

__global__ void __launch_bounds__(256, 1)
gemm_tc_k(const float* __restrict__ A, const float* __restrict__ W,
          const float* __restrict__ bias, float* __restrict__ C, int relu) {
    extern __shared__ float sh[];
    float* As = sh;                  // [128][136] tf32 bit patterns
    float* Ws = sh + SM_TILE;        // [128][136]
    float* bs = sh + 2 * SM_TILE;    // [128]

    int tid = threadIdx.x;
    int wid = tid >> 5;
    int lid = tid & 31;
    int row0 = blockIdx.x * 128;

    if (tid < FD) bs[tid] = bias[tid];

    const float4* A4 = (const float4*)A;
    const float4* W4 = (const float4*)W;
    #pragma unroll
    for (int it = 0; it < 16; it++) {
        int r = it * 8 + wid;
        int gr = row0 + r;
        float4 v = (gr < NN) ? A4[(size_t)gr * 32 + lid] : make_float4(0.f, 0.f, 0.f, 0.f);
        uint4 t;
        t.x = f2tf32(v.x); t.y = f2tf32(v.y); t.z = f2tf32(v.z); t.w = f2tf32(v.w);
        *(uint4*)&As[r * SM_STRIDE + lid * 4] = t;

        float4 w = W4[(size_t)r * 32 + lid];
        uint4 tw;
        tw.x = f2tf32(w.x); tw.y = f2tf32(w.y); tw.z = f2tf32(w.z); tw.w = f2tf32(w.w);
        *(uint4*)&Ws[r * SM_STRIDE + lid * 4] = tw;
    }
    __syncthreads();

    int warp_m = wid & 3;
    int warp_n = wid >> 2;
    int tig = lid & 3;
    int gid = lid >> 2;

    float c[2][8][4];
    #pragma unroll
    for (int mt = 0; mt < 2; mt++)
        #pragma unroll
        for (int nt = 0; nt < 8; nt++)
            #pragma unroll
            for (int j = 0; j < 4; j++) c[mt][nt][j] = 0.f;

    #pragma unroll 4
    for (int k0 = 0; k0 < 16; k0++) {
        int kc = k0 * 8 + tig;
        uint32_t a[2][4];
        #pragma unroll
        for (int mt = 0; mt < 2; mt++) {
            int rb = warp_m * 32 + mt * 16 + gid;
            a[mt][0] = __float_as_uint(As[rb * SM_STRIDE + kc]);
            a[mt][1] = __float_as_uint(As[(rb + 8) * SM_STRIDE + kc]);
            a[mt][2] = __float_as_uint(As[rb * SM_STRIDE + kc + 4]);
            a[mt][3] = __float_as_uint(As[(rb + 8) * SM_STRIDE + kc + 4]);
        }
        uint32_t b[8][2];
        #pragma unroll
        for (int nt = 0; nt < 8; nt++) {
            int n = warp_n * 64 + nt * 8 + gid;
            b[nt][0] = __float_as_uint(Ws[kc * SM_STRIDE + n]);
            b[nt][1] = __float_as_uint(Ws[(kc + 4) * SM_STRIDE + n]);
        }
        #pragma unroll
        for (int mt = 0; mt < 2; mt++)
            #pragma unroll
            for (int nt = 0; nt < 8; nt++)
                MMA_TF32(c[mt][nt], a[mt], b[nt]);
    }

    #pragma unroll
    for (int mt = 0; mt < 2; mt++) {
        int rg = row0 + warp_m * 32 + mt * 16 + gid;
        #pragma unroll
        for (int nt = 0; nt < 8; nt++) {
            int col = warp_n * 64 + nt * 8 + tig * 2;
            float2 o0, o1;
            o0.x = c[mt][nt][0] + bs[col];
            o0.y = c[mt][nt][1] + bs[col + 1];
            o1.x = c[mt][nt][2] + bs[col];
            o1.y = c[mt][nt][3] + bs[col + 1];
            if (relu) {
                o0.x = fmaxf(o0.x, 0.f); o0.y = fmaxf(o0.y, 0.f);
                o1.x = fmaxf(o1.x, 0.f); o1.y = fmaxf(o1.y, 0.f);
            }
            if (rg < NN)     *(float2*)&C[(size_t)rg * FD + col] = o0;
            if (rg + 8 < NN) *(float2*)&C[(size_t)(rg + 8) * FD + col] = o1;
        }
    }
}

// ---------------- small zero kernels ----------------
__global__ void zero_all_k() {
    int i = blockIdx.x * blockDim.x + threadIdx.x;
    if (i < FD) { g_sum[i] = 0.f; g_sumsq[i] = 0.f; }
    if (i < NG) g_counts[i] = 0.f;
    if (i < NG * FD) g_pooled[i] = 0.f;
}

__global__ void zero_sums_k() {
    int i = threadIdx.x;
    if (i < FD) { g_sum[i] = 0.f; g_sumsq[i] = 0.f; }
}

// ---------------- BN statistics ----------------
__global__ void bnstats_k(const float* __restrict__ X) {
    int f = threadIdx.x;
    int chunk = (NN + gridDim.x - 1) / gridDim.x;
    int r0 = blockIdx.x * chunk;
    int r1 = min(r0 + chunk, NN);
    float a = 0.f, b = 0.f;
    for (int r = r0; r < r1; r++) {
        float v = X[(size_t)r * FD + f];
        a += v;
        b = fmaf(v, v, b);
    }
    atomicAdd(&g_sum[f], a);
    atomicAdd(&g_sumsq[f], b);
}

// ---------------- BN finalize ----------------
__global__ void bnfin_k(const float* __restrict__ gamma, const float* __restrict__ beta) {
    int f = threadIdx.x;
    float mean = g_sum[f] * (1.f / NN);
    float var = g_sumsq[f] * (1.f / NN) - mean * mean;
    float sc = gamma[f] * rsqrtf(var + BN_EPS);
    g_scale[f] = sc;
    g_shift[f] = beta[f] - mean * sc;
}

// ---------------- BN+ReLU (single output; gather reads it for self+neighbors) ----------
__global__ void bnrelu_k(const float4* __restrict__ X, float4* __restrict__ o1) {
    int i = blockIdx.x * blockDim.x + threadIdx.x;
    if (i >= NN * 32) return;
    int f = i & 31;
    float4 sc = ((const float4*)g_scale)[f];
    float4 sf = ((const float4*)g_shift)[f];
    float4 x = X[i];
    float4 v;
    v.x = fmaxf(fmaf(x.x, sc.x, sf.x), 0.f);
    v.y = fmaxf(fmaf(x.y, sc.y, sf.y), 0.f);
    v.z = fmaxf(fmaf(x.z, sc.z, sf.z), 0.f);
    v.w = fmaxf(fmaf(x.w, sc.w, sf.w), 0.f);
    o1[i] = v;
}

// ---------------- BN+ReLU fused with graph pooling ----------------
__global__ void bnpool_k(const float4* __restrict__ X, const int* __restrict__ batch) {
    int i = blockIdx.x * blockDim.x + threadIdx.x;
    if (i >= NN * 32) return;
    int f = i & 31;
    int node = i >> 5;
    float4 sc = ((const float4*)g_scale)[f];
    float4 sf = ((const float4*)g_shift)[f];
    float4 x = X[i];
    float4 v;
    v.x = fmaxf(fmaf(x.x, sc.x, sf.x), 0.f);
    v.y = fmaxf(fmaf(x.y, sc.y, sf.y), 0.f);
    v.z = fmaxf(fmaf(x.z, sc.z, sf.z), 0.f);
    v.w = fmaxf(fmaf(x.w, sc.w, sf.w), 0.f);
    int g = batch[node];
    if ((unsigned)g >= NG) return;
    float* p = g_pooled + (size_t)g * FD + f * 4;
    asm volatile("red.global.add.v4.f32 [%0], {%1, %2, %3, %4};"
                 :: "l"(p), "f"(v.x), "f"(v.y), "f"(v.z), "f"(v.w) : "memory");
}

// ---------------- per-graph node counts ----------------
__global__ void count_k(const int* __restrict__ batch) {
    int i = blockIdx.x * blockDim.x + threadIdx.x;
    if (i < NN) {
        int g = batch[i];
        if ((unsigned)g < NG) atomicAdd(&g_counts[g], 1.f);
    }
}

// ---------------- classifier + log_softmax ----------------
__global__ void final_k(const float* __restrict__ Wlin, const float* __restrict__ blin,
                        float* __restrict__ out) {
    __shared__ float Ws[FD * NC];
    __shared__ float bs[NC];
    int t = threadIdx.x;
    for (int i = t; i < FD * NC; i += 128) Ws[i] = Wlin[i];
    if (t < NC) bs[t] = blin[t];
    __syncthreads();

    int g = t;
    float inv = 1.f / fmaxf(g_counts[g], 1.f);
    float logits[NC];
    #pragma unroll
    for (int c = 0; c < NC; c++) logits[c] = bs[c];
    for (int k = 0; k < FD; k++) {
        float p = g_pooled[(size_t)g * FD + k] * inv;
        #pragma unroll
        for (int c = 0; c < NC; c++) logits[c] = fmaf(p, Ws[k * NC + c], logits[c]);
    }
    float m = logits[0];
    #pragma unroll
    for (int c = 1; c < NC; c++) m = fmaxf(m, logits[c]);
    float s = 0.f;
    #pragma unroll
    for (int c = 0; c < NC; c++) s += expf(logits[c] - m);
    float lse = m + logf(s);
    #pragma unroll
    for (int c = 0; c < NC; c++) out[(size_t)g * NC + c] = logits[c] - lse;
}

// ---------------- host launcher ----------------
extern "C" void kernel_launch(void* const* d_in, const int* in_sizes, int n_in,
                              void* d_out, int out_size) {
    const float* x = (const float*)d_in[0];
    const int* ei = (const int*)d_in[1];
    const int* batch = (const int*)d_in[2];
    const float* W1a = (const float*)d_in[3];
    const float* b1a = (const float*)d_in[4];
    const float* W1b = (const float*)d_in[5];
    const float* b1b = (const float*)d_in[6];
    const float* gamma1 = (const float*)d_in[7];
    const float* beta1 = (const float*)d_in[8];
    const float* W2a = (const float*)d_in[9];
    const float* b2a = (const float*)d_in[10];
    const float* W2b = (const float*)d_in[11];
    const float* b2b = (const float*)d_in[12];
    const float* gamma2 = (const float*)d_in[13];
    const float* beta2 = (const float*)d_in[14];
    const float* Wlin = (const float*)d_in[15];
    const float* blin = (const float*)d_in[16];
    float* out = (float*)d_out;

    float *bufA, *bufB, *bufC, *bufD;
    cudaGetSymbolAddress((void**)&bufA, g_bufA);
    cudaGetSymbolAddress((void**)&bufB, g_bufB);
    cudaGetSymbolAddress((void**)&bufC, g_bufC);
    cudaGetSymbolAddress((void**)&bufD, g_bufD);

    cudaFuncSetAttribute(gemm_tc_k, cudaFuncAttributeMaxDynamicSharedMemorySize, GEMM_SMEM);

    const int n4 = NN * 32;
    const int EW_BLOCKS = (n4 + 255) / 256;
    const int E_BLOCKS = (NE + 255) / 256;
    const int TC_BLOCKS = (NN + 127) / 128;
    const int GA_BLOCKS = (NN * 32 + 255) / 256;   // one warp per node

    zero_all_k<<<(NG * FD + 255) / 256, 256>>>();

    // ---- build dst-sorted CSR once; reused by both convs ----
    zero_deg_k<<<(NN + 255) / 256, 256>>>();
    hist_k<<<E_BLOCKS, 256>>>(ei);
    scanp1_k<<<SCAN_NB, SCAN_BLK>>>();
    scanp2_k<<<1, 256>>>();
    scanp3_k<<<SCAN_NB, SCAN_BLK>>>();
    fill_k<<<E_BLOCKS, 256>>>(ei);

    // ---- conv1 ----
    gather_k<<<GA_BLOCKS, 256>>>((const float4*)x, (const float4*)x, (float4*)bufA);
    gemm_tc_k<<<TC_BLOCKS, 256, GEMM_SMEM>>>(bufA, W1a, b1a, bufB, 1);
    gemm_tc_k<<<TC_BLOCKS, 256, GEMM_SMEM>>>(bufB, W1b, b1b, bufC, 0);
    bnstats_k<<<800, 128>>>(bufC);
    bnfin_k<<<1, 128>>>(gamma1, beta1);
    zero_sums_k<<<1, 128>>>();
    bnrelu_k<<<EW_BLOCKS, 256>>>((const float4*)bufC, (float4*)bufD);

    // ---- conv2 ----
    gather_k<<<GA_BLOCKS, 256>>>((const float4*)bufD, (const float4*)bufD, (float4*)bufA);
    gemm_tc_k<<<TC_BLOCKS, 256, GEMM_SMEM>>>(bufA, W2a, b2a, bufB, 1);
    gemm_tc_k<<<TC_BLOCKS, 256, GEMM_SMEM>>>(bufB, W2b, b2b, bufC, 0);
    bnstats_k<<<800, 128>>>(bufC);
    bnfin_k<<<1, 128>>>(gamma2, beta2);

    // ---- BN+ReLU fused with pooling, then classifier ----
    bnpool_k<<<EW_BLOCKS, 256>>>((const float4*)bufC, batch);
    count_k<<<(NN + 255) / 256, 256>>>(batch);
    final_k<<<1, 128>>>(Wlin, blin, out);
}

// round 14
// speedup vs baseline: 1.4508x; 1.0581x over previous
#include <cuda_runtime.h>
#include <math.h>
#include <cstdint>

#define NN 100000     // nodes
#define NE 800000     // edges
#define FD 128        // feature dim (in = hidden = 128)
#define NG 128        // graphs
#define NC 10         // classes
#define BN_EPS 1e-5f

// ---------------- device scratch (no allocation allowed) ----------------
__device__ float g_bufA[(size_t)NN * FD];   // aggregation accumulator / GEMM input
__device__ float g_bufC[(size_t)NN * FD];   // MLP out (pre-BN)
__device__ float g_bufD[(size_t)NN * FD];   // post BN+ReLU (gather source, conv2)
__device__ float g_sum[FD];
__device__ float g_sumsq[FD];
__device__ float g_scale[FD];
__device__ float g_shift[FD];
__device__ float g_pooled[NG * FD];
__device__ float g_counts[NG];
// CSR build scratch
#define SCAN_BLK 512
#define SCAN_NB ((NN + SCAN_BLK - 1) / SCAN_BLK)   // 196
__device__ int g_deg[NN];
__device__ int g_startO[NN + 1];
__device__ int g_cursor[NN];
__device__ int g_srcs[NE];
__device__ int g_partial[SCAN_NB];

// ================= CSR build (per launch; reused by both convs) =================
__global__ void zero_deg_k() {
    int i = blockIdx.x * blockDim.x + threadIdx.x;
    if (i < NN) g_deg[i] = 0;
}

__global__ void hist_k(const int* __restrict__ ei) {
    int e = blockIdx.x * blockDim.x + threadIdx.x;
    if (e >= NE) return;
    int d = ei[NE + e];
    if ((unsigned)d < NN) atomicAdd(&g_deg[d], 1);
}

// ---- 3-phase parallel exclusive scan over g_deg ----
__global__ void scanp1_k() {
    int t = threadIdx.x;
    int i = blockIdx.x * SCAN_BLK + t;
    int v = (i < NN) ? g_deg[i] : 0;
    #pragma unroll
    for (int o = 16; o; o >>= 1) v += __shfl_down_sync(~0u, v, o);
    __shared__ int ws[16];
    if ((t & 31) == 0) ws[t >> 5] = v;
    __syncthreads();
    if (t < 16) {
        int s = ws[t];
        #pragma unroll
        for (int o = 8; o; o >>= 1) s += __shfl_down_sync(0xffffu, s, o);
        if (t == 0) g_partial[blockIdx.x] = s;
    }
}

__global__ void scanp2_k() {
    int t = threadIdx.x;
    int lane = t & 31, w = t >> 5;
    int v = (t < SCAN_NB) ? g_partial[t] : 0;
    int x = v;
    #pragma unroll
    for (int o = 1; o < 32; o <<= 1) {
        int n = __shfl_up_sync(~0u, x, o);
        if (lane >= o) x += n;
    }
    __shared__ int ws[8];
    if (lane == 31) ws[w] = x;
    __syncthreads();
    if (w == 0) {
        int s = (lane < 8) ? ws[lane] : 0;
        #pragma unroll
        for (int o = 1; o < 8; o <<= 1) {
            int n = __shfl_up_sync(~0u, s, o);
            if (lane >= o) s += n;
        }
        if (lane < 8) ws[lane] = s;
    }
    __syncthreads();
    int incl = x + (w > 0 ? ws[w - 1] : 0);
    if (t < SCAN_NB) g_partial[t] = incl - v;
    if (t == SCAN_NB - 1) g_startO[NN] = incl;
}

__global__ void scanp3_k() {
    int t = threadIdx.x;
    int i = blockIdx.x * SCAN_BLK + t;
    int lane = t & 31, w = t >> 5;
    int v = (i < NN) ? g_deg[i] : 0;
    int x = v;
    #pragma unroll
    for (int o = 1; o < 32; o <<= 1) {
        int n = __shfl_up_sync(~0u, x, o);
        if (lane >= o) x += n;
    }
    __shared__ int ws[16];
    if (lane == 31) ws[w] = x;
    __syncthreads();
    if (w == 0) {
        int s = (lane < 16) ? ws[lane] : 0;
        #pragma unroll
        for (int o = 1; o < 16; o <<= 1) {
            int n = __shfl_up_sync(~0u, s, o);
            if (lane >= o) s += n;
        }
        if (lane < 16) ws[lane] = s;
    }
    __syncthreads();
    int excl = x - v + (w > 0 ? ws[w - 1] : 0) + g_partial[blockIdx.x];
    if (i < NN) { g_startO[i] = excl; g_cursor[i] = excl; }
}

__global__ void fill_k(const int* __restrict__ ei) {
    int e = blockIdx.x * blockDim.x + threadIdx.x;
    if (e >= NE) return;
    int s = ei[e];
    int d = ei[NE + e];
    if ((unsigned)s >= NN || (unsigned)d >= NN) return;
    int pos = atomicAdd(&g_cursor[d], 1);
    g_srcs[pos] = s;
}

// ---------------- CSR gather aggregation: out[n] = base[n] + sum_{s in N(n)} feat[s] ----
__global__ void gather_k(const float4* __restrict__ feat, const float4* __restrict__ base,
                         float4* __restrict__ out) {
    int warp = (blockIdx.x * blockDim.x + threadIdx.x) >> 5;
    if (warp >= NN) return;
    int lane = threadIdx.x & 31;
    float4 acc = base[(size_t)warp * 32 + lane];
    int j0 = g_startO[warp], j1 = g_startO[warp + 1];
    int j = j0;
    for (; j + 1 < j1; j += 2) {
        int s0 = g_srcs[j], s1 = g_srcs[j + 1];
        float4 v0 = feat[(size_t)s0 * 32 + lane];
        float4 v1 = feat[(size_t)s1 * 32 + lane];
        acc.x += v0.x + v1.x; acc.y += v0.y + v1.y;
        acc.z += v0.z + v1.z; acc.w += v0.w + v1.w;
    }
    if (j < j1) {
        int s0 = g_srcs[j];
        float4 v0 = feat[(size_t)s0 * 32 + lane];
        acc.x += v0.x; acc.y += v0.y; acc.z += v0.z; acc.w += v0.w;
    }
    out[(size_t)warp * 32 + lane] = acc;
}

// ================= fused tf32 MLP GEMM: C = relu(A@Wa+ba)@Wb + bb =================
#define SM_STRIDE 136
#define SM_TILE (128 * SM_STRIDE)                  // floats per tile
#define GEMM_SMEM ((2 * SM_TILE + 2 * FD) * 4)     // slot0 + slot1 + ba + bb

__device__ __forceinline__ uint32_t f2tf32(float f) {
    uint32_t u;
    asm("cvt.rna.tf32.f32 %0, %1;" : "=r"(u) : "f"(f));
    return u;
}

#define MMA_TF32(Cf, Af, Bf)                                                   \
    asm volatile("mma.sync.aligned.m16n8k8.row.col.f32.tf32.tf32.f32 "         \
                 "{%0,%1,%2,%3}, {%4,%5,%6,%7}, {%8,%9}, {%0,%1,%2,%3};"       \
                 : "+f"((Cf)[0]), "+f"((Cf)[1]), "+f"((Cf)[2]), "+f"((Cf)[3])  \
                 : "r"((Af)[0]), "r"((Af)[1]), "r"((Af)[2]), "r"((Af)[3]),     \
                   "r"((Bf)[0]), "r"((Bf)[1]))

// one 128x128x128 MMA pass: c += As(128x128) @ Ws(128x128)^T-laid tiles
__device__ __forceinline__ void mma_pass(const float* As, const float* Ws,
                                         float c[2][8][4], int warp_m, int warp_n,
                                         int tig, int gid) {
    #pragma unroll 4
    for (int k0 = 0; k0 < 16; k0++) {
        int kc = k0 * 8 + tig;
        uint32_t a[2][4];
        #pragma unroll
        for (int mt = 0; mt < 2; mt++) {
            int rb = warp_m * 32 + mt * 16 + gid;
            a[mt][0] = __float_as_uint(As[rb * SM_STRIDE + kc]);
            a[mt][1] = __float_as_uint(As[(rb + 8) * SM_STRIDE + kc]);
            a[mt][2] = __float_as_uint(As[rb * SM_STRIDE + kc + 4]);
            a[mt][3] = __float_as_uint(As[(rb + 8) * SM_STRIDE + kc + 4]);
        }
        uint32_t b[8][2];
        #pragma unroll
        for (int nt = 0; nt < 8; nt++) {
            int n = warp_n * 64 + nt * 8 + gid;
            b[nt][0] = __float_as_uint(Ws[kc * SM_STRIDE + n]);
            b[nt][1] = __float_as_uint(Ws[(kc + 4) * SM_STRIDE + n]);
        }
        #pragma unroll
        for (int mt = 0; mt < 2; mt++)
            #pragma unroll
            for (int nt = 0; nt < 8; nt++)
                MMA_TF32(c[mt][nt], a[mt], b[nt]);
    }
}

__global__ void __launch_bounds__(256, 1)
gemm_mlp_k(const float* __restrict__ A,
           const float* __restrict__ Wa, const float* __restrict__ ba,
           const float* __restrict__ Wb, const float* __restrict__ bb,
           float* __restrict__ C) {
    extern __shared__ float sh[];
    float* slot0 = sh;                    // A tile, then H tile
    float* slot1 = sh + SM_TILE;          // Wa tile, then Wb tile
    float* bsa = sh + 2 * SM_TILE;        // ba [128]
    float* bsb = bsa + FD;                // bb [128]

    int tid = threadIdx.x;
    int wid = tid >> 5;
    int lid = tid & 31;
    int row0 = blockIdx.x * 128;

    if (tid < FD) { bsa[tid] = ba[tid]; bsb[tid] = bb[tid]; }

    // ---- load A and Wa tiles (tf32-converted) ----
    const float4* A4 = (const float4*)A;
    const float4* Wa4 = (const float4*)Wa;
    #pragma unroll
    for (int it = 0; it < 16; it++) {
        int r = it * 8 + wid;
        int gr = row0 + r;
        float4 v = (gr < NN) ? A4[(size_t)gr * 32 + lid] : make_float4(0.f, 0.f, 0.f, 0.f);
        uint4 t;
        t.x = f2tf32(v.x); t.y = f2tf32(v.y); t.z = f2tf32(v.z); t.w = f2tf32(v.w);
        *(uint4*)&slot0[r * SM_STRIDE + lid * 4] = t;

        float4 w = Wa4[(size_t)r * 32 + lid];
        uint4 tw;
        tw.x = f2tf32(w.x); tw.y = f2tf32(w.y); tw.z = f2tf32(w.z); tw.w = f2tf32(w.w);
        *(uint4*)&slot1[r * SM_STRIDE + lid * 4] = tw;
    }
    __syncthreads();

    int warp_m = wid & 3;
    int warp_n = wid >> 2;
    int tig = lid & 3;
    int gid = lid >> 2;

    // ---- phase 1: H = A @ Wa ----
    float c[2][8][4];
    #pragma unroll
    for (int mt = 0; mt < 2; mt++)
        #pragma unroll
        for (int nt = 0; nt < 8; nt++)
            #pragma unroll
            for (int j = 0; j < 4; j++) c[mt][nt][j] = 0.f;

    mma_pass(slot0, slot1, c, warp_m, warp_n, tig, gid);
    __syncthreads();   // everyone done reading slot0/slot1

    // ---- write H = relu(c + ba) into slot0 (tf32 bits); load Wb into slot1 ----
    const float4* Wb4 = (const float4*)Wb;
    #pragma unroll
    for (int it = 0; it < 16; it++) {
        int r = it * 8 + wid;
        float4 w = Wb4[(size_t)r * 32 + lid];
        uint4 tw;
        tw.x = f2tf32(w.x); tw.y = f2tf32(w.y); tw.z = f2tf32(w.z); tw.w = f2tf32(w.w);
        *(uint4*)&slot1[r * SM_STRIDE + lid * 4] = tw;
    }
    #pragma unroll
    for (int mt = 0; mt < 2; mt++) {
        int r = warp_m * 32 + mt * 16 + gid;
        #pragma unroll
        for (int nt = 0; nt < 8; nt++) {
            int col = warp_n * 64 + nt * 8 + tig * 2;
            uint2 h0, h1;
            h0.x = f2tf32(fmaxf(c[mt][nt][0] + bsa[col], 0.f));
            h0.y = f2tf32(fmaxf(c[mt][nt][1] + bsa[col + 1], 0.f));
            h1.x = f2tf32(fmaxf(c[mt][nt][2] + bsa[col], 0.f));
            h1.y = f2tf32(fmaxf(c[mt][nt][3] + bsa[col + 1], 0.f));
            *(uint2*)&slot0[r * SM_STRIDE + col] = h0;
            *(uint2*)&slot0[(r + 8) * SM_STRIDE + col] = h1;
        }
    }
    __syncthreads();

    // ---- phase 2: C = H @ Wb ----
    #pragma unroll
    for (int mt = 0; mt < 2; mt++)
        #pragma unroll
        for (int nt = 0; nt < 8; nt++)
            #pragma unroll
            for (int j = 0; j < 4; j++) c[mt][nt][j] = 0.f;

    mma_pass(slot0, slot1, c, warp_m, warp_n, tig, gid);

    // ---- epilogue: + bb, store ----
    #pragma unroll
    for (int mt = 0; mt < 2; mt++) {
        int rg = row0 + warp_m * 32 + mt * 16 + gid;
        #pragma unroll
        for (int nt = 0; nt < 8; nt++) {
            int col = warp_n * 64 + nt * 8 + tig * 2;
            float2 o0, o1;
            o0.x = c[mt][nt][0] + bsb[col];
            o0.y = c[mt][nt][1] + bsb[col + 1];
            o1.x = c[mt][nt][2] + bsb[col];
            o1.y = c[mt][nt][3] + bsb[col + 1];
            if (rg < NN)     *(float2*)&C[(size_t)rg * FD + col] = o0;
            if (rg + 8 < NN) *(float2*)&C[(size_t)(rg + 8) * FD + col] = o1;
        }
    }
}

// ---------------- small zero kernels ----------------
__global__ void zero_all_k() {
    int i = blockIdx.x * blockDim.x + threadIdx.x;
    if (i < FD) { g_sum[i] = 0.f; g_sumsq[i] = 0.f; }
    if (i < NG) g_counts[i] = 0.f;
    if (i < NG * FD) g_pooled[i] = 0.f;
}

__global__ void zero_sums_k() {
    int i = threadIdx.x;
    if (i < FD) { g_sum[i] = 0.f; g_sumsq[i] = 0.f; }
}

// ---------------- BN statistics ----------------
__global__ void bnstats_k(const float* __restrict__ X) {
    int f = threadIdx.x;
    int chunk = (NN + gridDim.x - 1) / gridDim.x;
    int r0 = blockIdx.x * chunk;
    int r1 = min(r0 + chunk, NN);
    float a = 0.f, b = 0.f;
    for (int r = r0; r < r1; r++) {
        float v = X[(size_t)r * FD + f];
        a += v;
        b = fmaf(v, v, b);
    }
    atomicAdd(&g_sum[f], a);
    atomicAdd(&g_sumsq[f], b);
}

// ---------------- BN finalize ----------------
__global__ void bnfin_k(const float* __restrict__ gamma, const float* __restrict__ beta) {
    int f = threadIdx.x;
    float mean = g_sum[f] * (1.f / NN);
    float var = g_sumsq[f] * (1.f / NN) - mean * mean;
    float sc = gamma[f] * rsqrtf(var + BN_EPS);
    g_scale[f] = sc;
    g_shift[f] = beta[f] - mean * sc;
}

// ---------------- BN+ReLU ----------------
__global__ void bnrelu_k(const float4* __restrict__ X, float4* __restrict__ o1) {
    int i = blockIdx.x * blockDim.x + threadIdx.x;
    if (i >= NN * 32) return;
    int f = i & 31;
    float4 sc = ((const float4*)g_scale)[f];
    float4 sf = ((const float4*)g_shift)[f];
    float4 x = X[i];
    float4 v;
    v.x = fmaxf(fmaf(x.x, sc.x, sf.x), 0.f);
    v.y = fmaxf(fmaf(x.y, sc.y, sf.y), 0.f);
    v.z = fmaxf(fmaf(x.z, sc.z, sf.z), 0.f);
    v.w = fmaxf(fmaf(x.w, sc.w, sf.w), 0.f);
    o1[i] = v;
}

// ---------------- BN+ReLU fused with graph pooling ----------------
__global__ void bnpool_k(const float4* __restrict__ X, const int* __restrict__ batch) {
    int i = blockIdx.x * blockDim.x + threadIdx.x;
    if (i >= NN * 32) return;
    int f = i & 31;
    int node = i >> 5;
    float4 sc = ((const float4*)g_scale)[f];
    float4 sf = ((const float4*)g_shift)[f];
    float4 x = X[i];
    float4 v;
    v.x = fmaxf(fmaf(x.x, sc.x, sf.x), 0.f);
    v.y = fmaxf(fmaf(x.y, sc.y, sf.y), 0.f);
    v.z = fmaxf(fmaf(x.z, sc.z, sf.z), 0.f);
    v.w = fmaxf(fmaf(x.w, sc.w, sf.w), 0.f);
    int g = batch[node];
    if ((unsigned)g >= NG) return;
    float* p = g_pooled + (size_t)g * FD + f * 4;
    asm volatile("red.global.add.v4.f32 [%0], {%1, %2, %3, %4};"
                 :: "l"(p), "f"(v.x), "f"(v.y), "f"(v.z), "f"(v.w) : "memory");
}

// ---------------- per-graph node counts ----------------
__global__ void count_k(const int* __restrict__ batch) {
    int i = blockIdx.x * blockDim.x + threadIdx.x;
    if (i < NN) {
        int g = batch[i];
        if ((unsigned)g < NG) atomicAdd(&g_counts[g], 1.f);
    }
}

// ---------------- classifier + log_softmax ----------------
__global__ void final_k(const float* __restrict__ Wlin, const float* __restrict__ blin,
                        float* __restrict__ out) {
    __shared__ float Ws[FD * NC];
    __shared__ float bs[NC];
    int t = threadIdx.x;
    for (int i = t; i < FD * NC; i += 128) Ws[i] = Wlin[i];
    if (t < NC) bs[t] = blin[t];
    __syncthreads();

    int g = t;
    float inv = 1.f / fmaxf(g_counts[g], 1.f);
    float logits[NC];
    #pragma unroll
    for (int c = 0; c < NC; c++) logits[c] = bs[c];
    for (int k = 0; k < FD; k++) {
        float p = g_pooled[(size_t)g * FD + k] * inv;
        #pragma unroll
        for (int c = 0; c < NC; c++) logits[c] = fmaf(p, Ws[k * NC + c], logits[c]);
    }
    float m = logits[0];
    #pragma unroll
    for (int c = 1; c < NC; c++) m = fmaxf(m, logits[c]);
    float s = 0.f;
    #pragma unroll
    for (int c = 0; c < NC; c++) s += expf(logits[c] - m);
    float lse = m + logf(s);
    #pragma unroll
    for (int c = 0; c < NC; c++) out[(size_t)g * NC + c] = logits[c] - lse;
}

// ---------------- host launcher ----------------
extern "C" void kernel_launch(void* const* d_in, const int* in_sizes, int n_in,
                              void* d_out, int out_size) {
    const float* x = (const float*)d_in[0];
    const int* ei = (const int*)d_in[1];
    const int* batch = (const int*)d_in[2];
    const float* W1a = (const float*)d_in[3];
    const float* b1a = (const float*)d_in[4];
    const float* W1b = (const float*)d_in[5];
    const float* b1b = (const float*)d_in[6];
    const float* gamma1 = (const float*)d_in[7];
    const float* beta1 = (const float*)d_in[8];
    const float* W2a = (const float*)d_in[9];
    const float* b2a = (const float*)d_in[10];
    const float* W2b = (const float*)d_in[11];
    const float* b2b = (const float*)d_in[12];
    const float* gamma2 = (const float*)d_in[13];
    const float* beta2 = (const float*)d_in[14];
    const float* Wlin = (const float*)d_in[15];
    const float* blin = (const float*)d_in[16];
    float* out = (float*)d_out;

    float *bufA, *bufC, *bufD;
    cudaGetSymbolAddress((void**)&bufA, g_bufA);
    cudaGetSymbolAddress((void**)&bufC, g_bufC);
    cudaGetSymbolAddress((void**)&bufD, g_bufD);

    cudaFuncSetAttribute(gemm_mlp_k, cudaFuncAttributeMaxDynamicSharedMemorySize, GEMM_SMEM);

    const int n4 = NN * 32;
    const int EW_BLOCKS = (n4 + 255) / 256;
    const int E_BLOCKS = (NE + 255) / 256;
    const int TC_BLOCKS = (NN + 127) / 128;
    const int GA_BLOCKS = (NN * 32 + 255) / 256;

    zero_all_k<<<(NG * FD + 255) / 256, 256>>>();

    // ---- build dst-sorted CSR once; reused by both convs ----
    zero_deg_k<<<(NN + 255) / 256, 256>>>();
    hist_k<<<E_BLOCKS, 256>>>(ei);
    scanp1_k<<<SCAN_NB, SCAN_BLK>>>();
    scanp2_k<<<1, 256>>>();
    scanp3_k<<<SCAN_NB, SCAN_BLK>>>();
    fill_k<<<E_BLOCKS, 256>>>(ei);

    // ---- conv1 ----
    gather_k<<<GA_BLOCKS, 256>>>((const float4*)x, (const float4*)x, (float4*)bufA);
    gemm_mlp_k<<<TC_BLOCKS, 256, GEMM_SMEM>>>(bufA, W1a, b1a, W1b, b1b, bufC);
    bnstats_k<<<800, 128>>>(bufC);
    bnfin_k<<<1, 128>>>(gamma1, beta1);
    zero_sums_k<<<1, 128>>>();
    bnrelu_k<<<EW_BLOCKS, 256>>>((const float4*)bufC, (float4*)bufD);

    // ---- conv2 ----
    gather_k<<<GA_BLOCKS, 256>>>((const float4*)bufD, (const float4*)bufD, (float4*)bufA);
    gemm_mlp_k<<<TC_BLOCKS, 256, GEMM_SMEM>>>(bufA, W2a, b2a, W2b, b2b, bufC);
    bnstats_k<<<800, 128>>>(bufC);
    bnfin_k<<<1, 128>>>(gamma2, beta2);

    // ---- BN+ReLU fused with pooling, then classifier ----
    bnpool_k<<<EW_BLOCKS, 256>>>((const float4*)bufC, batch);
    count_k<<<(NN + 255) / 256, 256>>>(batch);
    final_k<<<1, 128>>>(Wlin, blin, out);
}